// round 1
// baseline (speedup 1.0000x reference)
#include <cuda_runtime.h>
#include <cuda_bf16.h>
#include <cstdint>

// Problem constants
#define BATCH   4
#define TSEQ    2048
#define CDIM    1024
#define NHEAD   16
#define HDIM    64
#define FDIM    4096
#define MROWS   (BATCH * TSEQ)          // 8192
#define SM_SCALE 0.03125f               // C^-0.5 = 1/32

// ---------------- scratch (static device globals; no allocation) ----------------
__device__ float g_h   [MROWS * CDIM];   // LN output (reused for LN1 and LN2)
__device__ float g_q   [MROWS * CDIM];   // [B,T,H,D]
__device__ float g_k   [MROWS * CDIM];
__device__ float g_v   [MROWS * CDIM];
__device__ float g_attn[MROWS * CDIM];   // [B,T,H,D] == concat-heads [M,C]
__device__ float g_x1  [MROWS * CDIM];   // x + attn@Wp + bp
__device__ float g_ff  [MROWS * FDIM];   // relu(h@W1+b1)
__device__ float g_wq  [CDIM * CDIM];    // packed [C, H*D]
__device__ float g_wk  [CDIM * CDIM];
__device__ float g_wv  [CDIM * CDIM];

// ---------------- pack Wq/Wk/Wv from [H,C,D] to [C, H*D] ----------------
__global__ void pack_w_kernel(const float* __restrict__ Wq, const float* __restrict__ Wk,
                              const float* __restrict__ Wv) {
    int idx = blockIdx.x * 256 + threadIdx.x;   // over C*C = 1M
    int h = idx >> 16;            // / (C*D) = 65536
    int c = (idx >> 6) & 1023;
    int d = idx & 63;
    int o = c * CDIM + h * HDIM + d;
    g_wq[o] = Wq[idx];
    g_wk[o] = Wk[idx];
    g_wv[o] = Wv[idx];
}

// ---------------- layernorm: one block (256 thr) per row of 1024 ----------------
__global__ void layernorm_kernel(const float* __restrict__ x, const float* __restrict__ g,
                                 const float* __restrict__ b, float* __restrict__ out) {
    const int row = blockIdx.x;
    const int t = threadIdx.x;                  // 0..255
    const size_t off = (size_t)row * CDIM + t * 4;
    float4 v = *(const float4*)(x + off);
    float s  = v.x + v.y + v.z + v.w;
    float ss = fmaf(v.x, v.x, fmaf(v.y, v.y, fmaf(v.z, v.z, v.w * v.w)));
#pragma unroll
    for (int o = 16; o; o >>= 1) {
        s  += __shfl_xor_sync(0xffffffffu, s,  o);
        ss += __shfl_xor_sync(0xffffffffu, ss, o);
    }
    __shared__ float ws[8], wss[8];
    __shared__ float s_mu, s_rs;
    int lane = t & 31, wid = t >> 5;
    if (lane == 0) { ws[wid] = s; wss[wid] = ss; }
    __syncthreads();
    if (t == 0) {
        float S = 0.f, SS = 0.f;
#pragma unroll
        for (int i = 0; i < 8; ++i) { S += ws[i]; SS += wss[i]; }
        float mu  = S * (1.f / CDIM);
        float var = SS * (1.f / CDIM) - mu * mu;
        s_mu = mu;
        s_rs = rsqrtf(var + 1e-5f);
    }
    __syncthreads();
    float mu = s_mu, rs = s_rs;
    float4 gv = *(const float4*)(g + t * 4);
    float4 bv = *(const float4*)(b + t * 4);
    float4 ov;
    ov.x = (v.x - mu) * rs * gv.x + bv.x;
    ov.y = (v.y - mu) * rs * gv.y + bv.y;
    ov.z = (v.z - mu) * rs * gv.z + bv.z;
    ov.w = (v.w - mu) * rs * gv.w + bv.w;
    *(float4*)(out + off) = ov;
}

// ---------------- SGEMM: C = A[MxK] * B[KxN] (+bias)(+relu)(+residual) ----------------
// 128x128 block tile, BK=8, 256 threads, 8x8 per-thread microtile.
// EPI: 0 = none, 2 = bias+relu, 3 = bias+residual
template <int EPI>
__global__ __launch_bounds__(256, 2)
void sgemm128_kernel(const float* __restrict__ A, const float* __restrict__ Bm,
                     float* __restrict__ Cm, const float* __restrict__ bias,
                     const float* __restrict__ res, int M, int N, int K) {
    __shared__ float As[8][132];   // padded
    __shared__ float Bs[8][128];

    const int tid = threadIdx.x;
    const int row0 = blockIdx.y * 128;
    const int col0 = blockIdx.x * 128;

    const int arow = tid >> 1;
    const int acol = (tid & 1) * 4;
    const int brow = tid >> 5;
    const int bcol = (tid & 31) * 4;
    const int tx = tid & 15;       // 0..15 -> cols
    const int ty = tid >> 4;       // 0..15 -> rows

    const float* Aptr = A + (size_t)(row0 + arow) * K + acol;
    const float* Bptr = Bm + (size_t)brow * N + col0 + bcol;

    float acc[8][8];
#pragma unroll
    for (int i = 0; i < 8; ++i)
#pragma unroll
        for (int j = 0; j < 8; ++j) acc[i][j] = 0.f;

    for (int k0 = 0; k0 < K; k0 += 8) {
        float4 av = *(const float4*)(Aptr + k0);
        float4 bv = *(const float4*)(Bptr + (size_t)k0 * N);
        As[acol + 0][arow] = av.x;
        As[acol + 1][arow] = av.y;
        As[acol + 2][arow] = av.z;
        As[acol + 3][arow] = av.w;
        *(float4*)&Bs[brow][bcol] = bv;
        __syncthreads();
#pragma unroll
        for (int kk = 0; kk < 8; ++kk) {
            float4 a0 = *(const float4*)&As[kk][ty * 8];
            float4 a1 = *(const float4*)&As[kk][ty * 8 + 4];
            float4 b0 = *(const float4*)&Bs[kk][tx * 8];
            float4 b1 = *(const float4*)&Bs[kk][tx * 8 + 4];
            float ar[8] = {a0.x, a0.y, a0.z, a0.w, a1.x, a1.y, a1.z, a1.w};
            float br[8] = {b0.x, b0.y, b0.z, b0.w, b1.x, b1.y, b1.z, b1.w};
#pragma unroll
            for (int i = 0; i < 8; ++i)
#pragma unroll
                for (int j = 0; j < 8; ++j)
                    acc[i][j] = fmaf(ar[i], br[j], acc[i][j]);
        }
        __syncthreads();
    }

#pragma unroll
    for (int i = 0; i < 8; ++i) {
        const int r = row0 + ty * 8 + i;
#pragma unroll
        for (int j = 0; j < 8; j += 4) {
            const int c = col0 + tx * 8 + j;
            float4 v = make_float4(acc[i][j], acc[i][j + 1], acc[i][j + 2], acc[i][j + 3]);
            if (EPI >= 2) {
                v.x += bias[c];     v.y += bias[c + 1];
                v.z += bias[c + 2]; v.w += bias[c + 3];
            }
            if (EPI == 2) {
                v.x = fmaxf(v.x, 0.f); v.y = fmaxf(v.y, 0.f);
                v.z = fmaxf(v.z, 0.f); v.w = fmaxf(v.w, 0.f);
            }
            if (EPI == 3) {
                float4 rv = *(const float4*)(res + (size_t)r * N + c);
                v.x += rv.x; v.y += rv.y; v.z += rv.z; v.w += rv.w;
            }
            *(float4*)(Cm + (size_t)r * N + c) = v;
        }
    }
}

// ---------------- flash attention (fp32), causal ----------------
// Q/K/V layout [B,T,H,D] i.e. row (b*T+t), col h*D+d within C.
// grid: (T/64, H, B), 256 threads (8 warps). Warp w owns rows w*8..w*8+7.
// Lane l owns key/dim slots l and l+32.
__global__ __launch_bounds__(256, 3)
void flash_attn_kernel(const float* __restrict__ Q, const float* __restrict__ K,
                       const float* __restrict__ V, float* __restrict__ O) {
    extern __shared__ float sm[];
    float* Qs = sm;                 // [64][65]
    float* Ks = sm + 64 * 65;       // [64][65]
    float* Vs = sm + 2 * 64 * 65;   // [64][65]
    float* Ps = sm + 3 * 64 * 65;   // [64][64]

    const int qb = blockIdx.x, h = blockIdx.y, b = blockIdx.z;
    const int tid = threadIdx.x, lane = tid & 31, w = tid >> 5;
    const int q0 = qb * 64;
    const size_t base = (size_t)b * TSEQ * CDIM + h * HDIM;

    // load Q tile
    for (int i = tid; i < 64 * 16; i += 256) {
        int r = i >> 4, c4 = (i & 15) * 4;
        float4 qv = *(const float4*)(Q + base + (size_t)(q0 + r) * CDIM + c4);
        Qs[r * 65 + c4 + 0] = qv.x; Qs[r * 65 + c4 + 1] = qv.y;
        Qs[r * 65 + c4 + 2] = qv.z; Qs[r * 65 + c4 + 3] = qv.w;
    }

    float m_i[8], l_i[8], o0[8], o1[8];
#pragma unroll
    for (int i = 0; i < 8; ++i) { m_i[i] = -1e30f; l_i[i] = 0.f; o0[i] = 0.f; o1[i] = 0.f; }
    const int rbase = w * 8;
    const int s0 = lane, s1 = lane + 32;

    for (int j = 0; j <= qb; ++j) {
        __syncthreads();   // previous iter's Ks/Vs/Ps consumers done
        const int k0 = j * 64;
        for (int i = tid; i < 64 * 16; i += 256) {
            int r = i >> 4, c4 = (i & 15) * 4;
            float4 kv = *(const float4*)(K + base + (size_t)(k0 + r) * CDIM + c4);
            Ks[r * 65 + c4 + 0] = kv.x; Ks[r * 65 + c4 + 1] = kv.y;
            Ks[r * 65 + c4 + 2] = kv.z; Ks[r * 65 + c4 + 3] = kv.w;
            float4 vv = *(const float4*)(V + base + (size_t)(k0 + r) * CDIM + c4);
            Vs[r * 65 + c4 + 0] = vv.x; Vs[r * 65 + c4 + 1] = vv.y;
            Vs[r * 65 + c4 + 2] = vv.z; Vs[r * 65 + c4 + 3] = vv.w;
        }
        __syncthreads();

        // S = Q K^T for my 8 rows x 2 key cols
        float acc0[8], acc1[8];
#pragma unroll
        for (int i = 0; i < 8; ++i) { acc0[i] = 0.f; acc1[i] = 0.f; }
#pragma unroll 8
        for (int d = 0; d < 64; ++d) {
            float kv0 = Ks[s0 * 65 + d];
            float kv1 = Ks[s1 * 65 + d];
#pragma unroll
            for (int i = 0; i < 8; ++i) {
                float qv = Qs[(rbase + i) * 65 + d];
                acc0[i] = fmaf(qv, kv0, acc0[i]);
                acc1[i] = fmaf(qv, kv1, acc1[i]);
            }
        }

        const bool diag = (j == qb);
#pragma unroll
        for (int i = 0; i < 8; ++i) {
            const int r = rbase + i;
            float v0 = acc0[i] * SM_SCALE;
            float v1 = acc1[i] * SM_SCALE;
            if (diag) {
                if (k0 + s0 > q0 + r) v0 = -1e30f;
                if (k0 + s1 > q0 + r) v1 = -1e30f;
            }
            float mx = fmaxf(v0, v1);
#pragma unroll
            for (int o = 16; o; o >>= 1) mx = fmaxf(mx, __shfl_xor_sync(0xffffffffu, mx, o));
            float mnew = fmaxf(m_i[i], mx);
            float p0 = __expf(v0 - mnew);
            float p1 = __expf(v1 - mnew);
            float alpha = __expf(m_i[i] - mnew);
            m_i[i] = mnew;
            float ps = p0 + p1;
#pragma unroll
            for (int o = 16; o; o >>= 1) ps += __shfl_xor_sync(0xffffffffu, ps, o);
            l_i[i] = l_i[i] * alpha + ps;
            o0[i] *= alpha;
            o1[i] *= alpha;
            Ps[r * 64 + s0] = p0;
            Ps[r * 64 + s1] = p1;
        }
        __syncwarp();

        // O += P V
#pragma unroll 8
        for (int s = 0; s < 64; ++s) {
            float v0 = Vs[s * 65 + s0];
            float v1 = Vs[s * 65 + s1];
#pragma unroll
            for (int i = 0; i < 8; ++i) {
                float p = Ps[(rbase + i) * 64 + s];
                o0[i] = fmaf(p, v0, o0[i]);
                o1[i] = fmaf(p, v1, o1[i]);
            }
        }
        __syncwarp();
    }

#pragma unroll
    for (int i = 0; i < 8; ++i) {
        const int r = rbase + i;
        float inv = 1.f / l_i[i];
        O[base + (size_t)(q0 + r) * CDIM + s0] = o0[i] * inv;
        O[base + (size_t)(q0 + r) * CDIM + s1] = o1[i] * inv;
    }
}

// ---------------- launch ----------------
extern "C" void kernel_launch(void* const* d_in, const int* in_sizes, int n_in,
                              void* d_out, int out_size) {
    (void)in_sizes; (void)n_in; (void)out_size;
    const float* x    = (const float*)d_in[0];
    const float* Wq   = (const float*)d_in[1];
    const float* Wk   = (const float*)d_in[2];
    const float* Wv   = (const float*)d_in[3];
    const float* Wp   = (const float*)d_in[4];
    const float* bp   = (const float*)d_in[5];
    const float* ln1g = (const float*)d_in[6];
    const float* ln1b = (const float*)d_in[7];
    const float* ln2g = (const float*)d_in[8];
    const float* ln2b = (const float*)d_in[9];
    const float* W1   = (const float*)d_in[10];
    const float* b1   = (const float*)d_in[11];
    const float* W2   = (const float*)d_in[12];
    const float* b2   = (const float*)d_in[13];
    float* out = (float*)d_out;

    float *h, *q, *k, *v, *attn, *x1, *ff, *pq, *pk, *pv;
    cudaGetSymbolAddress((void**)&h,    g_h);
    cudaGetSymbolAddress((void**)&q,    g_q);
    cudaGetSymbolAddress((void**)&k,    g_k);
    cudaGetSymbolAddress((void**)&v,    g_v);
    cudaGetSymbolAddress((void**)&attn, g_attn);
    cudaGetSymbolAddress((void**)&x1,   g_x1);
    cudaGetSymbolAddress((void**)&ff,   g_ff);
    cudaGetSymbolAddress((void**)&pq,   g_wq);
    cudaGetSymbolAddress((void**)&pk,   g_wk);
    cudaGetSymbolAddress((void**)&pv,   g_wv);

    // 1) pack QKV weights [H,C,D] -> [C,H*D]
    pack_w_kernel<<<(CDIM * CDIM) / 256, 256>>>(Wq, Wk, Wv);

    // 2) LN1
    layernorm_kernel<<<MROWS, 256>>>(x, ln1g, ln1b, h);

    // 3) Q,K,V projections
    dim3 gqkv(CDIM / 128, MROWS / 128);
    sgemm128_kernel<0><<<gqkv, 256>>>(h, pq, q, nullptr, nullptr, MROWS, CDIM, CDIM);
    sgemm128_kernel<0><<<gqkv, 256>>>(h, pk, k, nullptr, nullptr, MROWS, CDIM, CDIM);
    sgemm128_kernel<0><<<gqkv, 256>>>(h, pv, v, nullptr, nullptr, MROWS, CDIM, CDIM);

    // 4) attention
    size_t fasm = (size_t)(3 * 64 * 65 + 64 * 64) * sizeof(float);
    cudaFuncSetAttribute(flash_attn_kernel, cudaFuncAttributeMaxDynamicSharedMemorySize, (int)fasm);
    flash_attn_kernel<<<dim3(TSEQ / 64, NHEAD, BATCH), 256, fasm>>>(q, k, v, attn);

    // 5) output projection + residual: x1 = x + attn@Wp + bp
    sgemm128_kernel<3><<<gqkv, 256>>>(attn, Wp, x1, bp, x, MROWS, CDIM, CDIM);

    // 6) LN2
    layernorm_kernel<<<MROWS, 256>>>(x1, ln2g, ln2b, h);

    // 7) ff1 = relu(h@W1 + b1)
    dim3 gff1(FDIM / 128, MROWS / 128);
    sgemm128_kernel<2><<<gff1, 256>>>(h, W1, ff, b1, nullptr, MROWS, FDIM, CDIM);

    // 8) out = x1 + ff@W2 + b2
    sgemm128_kernel<3><<<gqkv, 256>>>(ff, W2, out, b2, x1, MROWS, CDIM, FDIM);
}

// round 2
// speedup vs baseline: 2.3312x; 2.3312x over previous
#include <cuda_runtime.h>
#include <cuda_bf16.h>
#include <cstdint>

// Problem constants
#define BATCH   4
#define TSEQ    2048
#define CDIM    1024
#define NHEAD   16
#define HDIM    64
#define FDIM    4096
#define MROWS   (BATCH * TSEQ)          // 8192
#define QKVDIM  (3 * CDIM)              // 3072
#define SM_SCALE 0.03125f               // C^-0.5 = 1/32

// ---------------- scratch (static device globals; no allocation) ----------------
__device__ float g_h   [MROWS * CDIM];    // LN output (reused for LN1 and LN2)
__device__ float g_qkv [MROWS * QKVDIM];  // [M, 3C]: q | k | v, each [B,T,H,D]
__device__ float g_attn[MROWS * CDIM];    // [B,T,H,D] == concat-heads [M,C]
__device__ float g_x1  [MROWS * CDIM];    // x + attn@Wp + bp
__device__ float g_ff  [MROWS * FDIM];    // relu(h@W1+b1)
__device__ float g_wqkv[CDIM * QKVDIM];   // packed [C, 3C]

// ---------------- pack Wq/Wk/Wv from [H,C,D] into [C, 3C] ----------------
__global__ void pack_w_kernel(const float* __restrict__ Wq, const float* __restrict__ Wk,
                              const float* __restrict__ Wv) {
    int idx = blockIdx.x * 256 + threadIdx.x;   // over C*C = 1M
    int h = idx >> 16;            // / (C*D) = 65536
    int c = (idx >> 6) & 1023;
    int d = idx & 63;
    int o = c * QKVDIM + h * HDIM + d;
    g_wqkv[o]            = Wq[idx];
    g_wqkv[o + CDIM]     = Wk[idx];
    g_wqkv[o + 2 * CDIM] = Wv[idx];
}

// ---------------- layernorm: one block (256 thr) per row of 1024 ----------------
__global__ void layernorm_kernel(const float* __restrict__ x, const float* __restrict__ g,
                                 const float* __restrict__ b, float* __restrict__ out) {
    const int row = blockIdx.x;
    const int t = threadIdx.x;                  // 0..255
    const size_t off = (size_t)row * CDIM + t * 4;
    float4 v = *(const float4*)(x + off);
    float s  = v.x + v.y + v.z + v.w;
    float ss = fmaf(v.x, v.x, fmaf(v.y, v.y, fmaf(v.z, v.z, v.w * v.w)));
#pragma unroll
    for (int o = 16; o; o >>= 1) {
        s  += __shfl_xor_sync(0xffffffffu, s,  o);
        ss += __shfl_xor_sync(0xffffffffu, ss, o);
    }
    __shared__ float ws[8], wss[8];
    __shared__ float s_mu, s_rs;
    int lane = t & 31, wid = t >> 5;
    if (lane == 0) { ws[wid] = s; wss[wid] = ss; }
    __syncthreads();
    if (t == 0) {
        float S = 0.f, SS = 0.f;
#pragma unroll
        for (int i = 0; i < 8; ++i) { S += ws[i]; SS += wss[i]; }
        float mu  = S * (1.f / CDIM);
        float var = SS * (1.f / CDIM) - mu * mu;
        s_mu = mu;
        s_rs = rsqrtf(var + 1e-5f);
    }
    __syncthreads();
    float mu = s_mu, rs = s_rs;
    float4 gv = *(const float4*)(g + t * 4);
    float4 bv = *(const float4*)(b + t * 4);
    float4 ov;
    ov.x = (v.x - mu) * rs * gv.x + bv.x;
    ov.y = (v.y - mu) * rs * gv.y + bv.y;
    ov.z = (v.z - mu) * rs * gv.z + bv.z;
    ov.w = (v.w - mu) * rs * gv.w + bv.w;
    *(float4*)(out + off) = ov;
}

// ---------------- TF32 tensor-core GEMM ----------------
// C[M,N] = A[M,K] @ B[K,N], 128x128 tile, BK=16, cp.async double buffer,
// 256 threads = 8 warps (2 x 4), warp tile 64x32, mma.m16n8k8.tf32.
// EPI: 0 = none, 2 = bias+relu, 3 = bias+residual
__device__ __forceinline__ uint32_t tf32c(float x) {
    uint32_t r;
    asm("cvt.rna.tf32.f32 %0, %1;" : "=r"(r) : "f"(x));
    return r;
}
__device__ __forceinline__ void cp16(void* smem, const void* gsrc) {
    uint32_t s = (uint32_t)__cvta_generic_to_shared(smem);
    asm volatile("cp.async.cg.shared.global [%0], [%1], 16;\n" :: "r"(s), "l"(gsrc));
}
__device__ __forceinline__ void mma_tf32(float* c, const uint32_t* a, const uint32_t* b) {
    asm volatile(
        "mma.sync.aligned.m16n8k8.row.col.f32.tf32.tf32.f32 "
        "{%0,%1,%2,%3}, {%4,%5,%6,%7}, {%8,%9}, {%0,%1,%2,%3};\n"
        : "+f"(c[0]), "+f"(c[1]), "+f"(c[2]), "+f"(c[3])
        : "r"(a[0]), "r"(a[1]), "r"(a[2]), "r"(a[3]), "r"(b[0]), "r"(b[1]));
}

#define AS_STRIDE 20    // conflict-free for A fragment loads (20*g mod 32 hits 8 distinct 4-blocks)
#define BS_STRIDE 136   // conflict-free for B fragment loads (8*k + n distinct)

template <int EPI>
__global__ __launch_bounds__(256, 2)
void tf32gemm_kernel(const float* __restrict__ A, const float* __restrict__ Bm,
                     float* __restrict__ Cm, const float* __restrict__ bias,
                     const float* __restrict__ res, int M, int N, int K) {
    __shared__ float As[2][128][AS_STRIDE];
    __shared__ float Bs[2][16][BS_STRIDE];

    const int tid  = threadIdx.x;
    const int lane = tid & 31, wid = tid >> 5;
    const int warpM = wid & 1;        // 0..1 -> M offset 0/64
    const int warpN = wid >> 1;       // 0..3 -> N offset 0/32/64/96
    const int row0 = blockIdx.y * 128, col0 = blockIdx.x * 128;
    const int g  = lane >> 2;         // groupID 0..7
    const int tg = lane & 3;          // threadID_in_group 0..3

    // gmem->smem loader indices (each thread: 2 x 16B for A, 2 x 16B for B)
    const int arow = tid >> 2, ac4 = (tid & 3) * 4;
    const int bkr  = tid >> 5, bn4 = (tid & 31) * 4;

    float acc[4][4][4];
#pragma unroll
    for (int mt = 0; mt < 4; ++mt)
#pragma unroll
        for (int nt = 0; nt < 4; ++nt)
#pragma unroll
            for (int r = 0; r < 4; ++r) acc[mt][nt][r] = 0.f;

#define LOAD_STAGE(s, k0)                                                            \
    do {                                                                             \
        cp16(&As[s][arow][ac4],      A + (size_t)(row0 + arow) * K + (k0) + ac4);    \
        cp16(&As[s][arow + 64][ac4], A + (size_t)(row0 + arow + 64) * K + (k0) + ac4);\
        cp16(&Bs[s][bkr][bn4],       Bm + (size_t)((k0) + bkr) * N + col0 + bn4);    \
        cp16(&Bs[s][bkr + 8][bn4],   Bm + (size_t)((k0) + bkr + 8) * N + col0 + bn4);\
        asm volatile("cp.async.commit_group;\n");                                    \
    } while (0)

    LOAD_STAGE(0, 0);
    const int KT = K >> 4;
    for (int kt = 0; kt < KT; ++kt) {
        if (kt + 1 < KT) {
            LOAD_STAGE((kt + 1) & 1, (kt + 1) << 4);
            asm volatile("cp.async.wait_group 1;\n");
        } else {
            asm volatile("cp.async.wait_group 0;\n");
        }
        __syncthreads();
        const int s = kt & 1;
#pragma unroll
        for (int ch = 0; ch < 2; ++ch) {
            const int kc = ch * 8;
            uint32_t a[4][4], b[4][2];
#pragma unroll
            for (int mt = 0; mt < 4; ++mt) {
                const int r = warpM * 64 + mt * 16 + g;
                const int c = kc + tg;
                a[mt][0] = tf32c(As[s][r][c]);
                a[mt][1] = tf32c(As[s][r + 8][c]);
                a[mt][2] = tf32c(As[s][r][c + 4]);
                a[mt][3] = tf32c(As[s][r + 8][c + 4]);
            }
#pragma unroll
            for (int nt = 0; nt < 4; ++nt) {
                const int n = warpN * 32 + nt * 8 + g;
                const int k = kc + tg;
                b[nt][0] = tf32c(Bs[s][k][n]);
                b[nt][1] = tf32c(Bs[s][k + 4][n]);
            }
#pragma unroll
            for (int mt = 0; mt < 4; ++mt)
#pragma unroll
                for (int nt = 0; nt < 4; ++nt)
                    mma_tf32(acc[mt][nt], a[mt], b[nt]);
        }
        __syncthreads();
    }
#undef LOAD_STAGE

    // epilogue
#pragma unroll
    for (int mt = 0; mt < 4; ++mt) {
#pragma unroll
        for (int nt = 0; nt < 4; ++nt) {
            const int r = row0 + warpM * 64 + mt * 16 + g;
            const int c = col0 + warpN * 32 + nt * 8 + 2 * tg;
            float2 v0 = make_float2(acc[mt][nt][0], acc[mt][nt][1]);   // row r
            float2 v1 = make_float2(acc[mt][nt][2], acc[mt][nt][3]);   // row r+8
            if (EPI >= 2) {
                float b0 = bias[c], b1 = bias[c + 1];
                v0.x += b0; v0.y += b1;
                v1.x += b0; v1.y += b1;
            }
            if (EPI == 2) {
                v0.x = fmaxf(v0.x, 0.f); v0.y = fmaxf(v0.y, 0.f);
                v1.x = fmaxf(v1.x, 0.f); v1.y = fmaxf(v1.y, 0.f);
            }
            if (EPI == 3) {
                float2 r0 = *(const float2*)(res + (size_t)r * N + c);
                float2 r1 = *(const float2*)(res + (size_t)(r + 8) * N + c);
                v0.x += r0.x; v0.y += r0.y;
                v1.x += r1.x; v1.y += r1.y;
            }
            *(float2*)(Cm + (size_t)r * N + c)       = v0;
            *(float2*)(Cm + (size_t)(r + 8) * N + c) = v1;
        }
    }
}

// ---------------- flash attention (fp32), causal ----------------
// Q/K/V live in g_qkv with row stride 3C: row (b*T+t), col h*D+d (+0/C/2C).
// grid: (T/64, H, B), 256 threads (8 warps). Warp w owns rows w*8..w*8+7.
// Lane l owns key/dim slots l and l+32.
__global__ __launch_bounds__(256, 3)
void flash_attn_kernel(const float* __restrict__ QKV, float* __restrict__ O) {
    extern __shared__ float sm[];
    float* Qs = sm;                 // [64][65]
    float* Ks = sm + 64 * 65;       // [64][65]
    float* Vs = sm + 2 * 64 * 65;   // [64][65]
    float* Ps = sm + 3 * 64 * 65;   // [64][64]

    const int qb = blockIdx.x, h = blockIdx.y, b = blockIdx.z;
    const int tid = threadIdx.x, lane = tid & 31, w = tid >> 5;
    const int q0 = qb * 64;
    const size_t base  = (size_t)b * TSEQ * QKVDIM + h * HDIM;
    const size_t obase = (size_t)b * TSEQ * CDIM + h * HDIM;
    const float* Q = QKV;
    const float* K = QKV + CDIM;
    const float* V = QKV + 2 * CDIM;

    // load Q tile
    for (int i = tid; i < 64 * 16; i += 256) {
        int r = i >> 4, c4 = (i & 15) * 4;
        float4 qv = *(const float4*)(Q + base + (size_t)(q0 + r) * QKVDIM + c4);
        Qs[r * 65 + c4 + 0] = qv.x; Qs[r * 65 + c4 + 1] = qv.y;
        Qs[r * 65 + c4 + 2] = qv.z; Qs[r * 65 + c4 + 3] = qv.w;
    }

    float m_i[8], l_i[8], o0[8], o1[8];
#pragma unroll
    for (int i = 0; i < 8; ++i) { m_i[i] = -1e30f; l_i[i] = 0.f; o0[i] = 0.f; o1[i] = 0.f; }
    const int rbase = w * 8;
    const int s0 = lane, s1 = lane + 32;

    for (int j = 0; j <= qb; ++j) {
        __syncthreads();   // previous iter's Ks/Vs/Ps consumers done
        const int k0 = j * 64;
        for (int i = tid; i < 64 * 16; i += 256) {
            int r = i >> 4, c4 = (i & 15) * 4;
            float4 kv = *(const float4*)(K + base + (size_t)(k0 + r) * QKVDIM + c4);
            Ks[r * 65 + c4 + 0] = kv.x; Ks[r * 65 + c4 + 1] = kv.y;
            Ks[r * 65 + c4 + 2] = kv.z; Ks[r * 65 + c4 + 3] = kv.w;
            float4 vv = *(const float4*)(V + base + (size_t)(k0 + r) * QKVDIM + c4);
            Vs[r * 65 + c4 + 0] = vv.x; Vs[r * 65 + c4 + 1] = vv.y;
            Vs[r * 65 + c4 + 2] = vv.z; Vs[r * 65 + c4 + 3] = vv.w;
        }
        __syncthreads();

        // S = Q K^T for my 8 rows x 2 key cols
        float acc0[8], acc1[8];
#pragma unroll
        for (int i = 0; i < 8; ++i) { acc0[i] = 0.f; acc1[i] = 0.f; }
#pragma unroll 8
        for (int d = 0; d < 64; ++d) {
            float kv0 = Ks[s0 * 65 + d];
            float kv1 = Ks[s1 * 65 + d];
#pragma unroll
            for (int i = 0; i < 8; ++i) {
                float qv = Qs[(rbase + i) * 65 + d];
                acc0[i] = fmaf(qv, kv0, acc0[i]);
                acc1[i] = fmaf(qv, kv1, acc1[i]);
            }
        }

        const bool diag = (j == qb);
#pragma unroll
        for (int i = 0; i < 8; ++i) {
            const int r = rbase + i;
            float v0 = acc0[i] * SM_SCALE;
            float v1 = acc1[i] * SM_SCALE;
            if (diag) {
                if (k0 + s0 > q0 + r) v0 = -1e30f;
                if (k0 + s1 > q0 + r) v1 = -1e30f;
            }
            float mx = fmaxf(v0, v1);
#pragma unroll
            for (int o = 16; o; o >>= 1) mx = fmaxf(mx, __shfl_xor_sync(0xffffffffu, mx, o));
            float mnew = fmaxf(m_i[i], mx);
            float p0 = __expf(v0 - mnew);
            float p1 = __expf(v1 - mnew);
            float alpha = __expf(m_i[i] - mnew);
            m_i[i] = mnew;
            float ps = p0 + p1;
#pragma unroll
            for (int o = 16; o; o >>= 1) ps += __shfl_xor_sync(0xffffffffu, ps, o);
            l_i[i] = l_i[i] * alpha + ps;
            o0[i] *= alpha;
            o1[i] *= alpha;
            Ps[r * 64 + s0] = p0;
            Ps[r * 64 + s1] = p1;
        }
        __syncwarp();

        // O += P V
#pragma unroll 8
        for (int s = 0; s < 64; ++s) {
            float v0 = Vs[s * 65 + s0];
            float v1 = Vs[s * 65 + s1];
#pragma unroll
            for (int i = 0; i < 8; ++i) {
                float p = Ps[(rbase + i) * 64 + s];
                o0[i] = fmaf(p, v0, o0[i]);
                o1[i] = fmaf(p, v1, o1[i]);
            }
        }
        __syncwarp();
    }

#pragma unroll
    for (int i = 0; i < 8; ++i) {
        const int r = rbase + i;
        float inv = 1.f / l_i[i];
        O[obase + (size_t)(q0 + r) * CDIM + s0] = o0[i] * inv;
        O[obase + (size_t)(q0 + r) * CDIM + s1] = o1[i] * inv;
    }
}

// ---------------- launch ----------------
extern "C" void kernel_launch(void* const* d_in, const int* in_sizes, int n_in,
                              void* d_out, int out_size) {
    (void)in_sizes; (void)n_in; (void)out_size;
    const float* x    = (const float*)d_in[0];
    const float* Wq   = (const float*)d_in[1];
    const float* Wk   = (const float*)d_in[2];
    const float* Wv   = (const float*)d_in[3];
    const float* Wp   = (const float*)d_in[4];
    const float* bp   = (const float*)d_in[5];
    const float* ln1g = (const float*)d_in[6];
    const float* ln1b = (const float*)d_in[7];
    const float* ln2g = (const float*)d_in[8];
    const float* ln2b = (const float*)d_in[9];
    const float* W1   = (const float*)d_in[10];
    const float* b1   = (const float*)d_in[11];
    const float* W2   = (const float*)d_in[12];
    const float* b2   = (const float*)d_in[13];
    float* out = (float*)d_out;

    float *h, *qkv, *attn, *x1, *ff, *wqkv;
    cudaGetSymbolAddress((void**)&h,    g_h);
    cudaGetSymbolAddress((void**)&qkv,  g_qkv);
    cudaGetSymbolAddress((void**)&attn, g_attn);
    cudaGetSymbolAddress((void**)&x1,   g_x1);
    cudaGetSymbolAddress((void**)&ff,   g_ff);
    cudaGetSymbolAddress((void**)&wqkv, g_wqkv);

    // 1) pack QKV weights [H,C,D] -> [C, 3C]
    pack_w_kernel<<<(CDIM * CDIM) / 256, 256>>>(Wq, Wk, Wv);

    // 2) LN1
    layernorm_kernel<<<MROWS, 256>>>(x, ln1g, ln1b, h);

    // 3) fused QKV projection: [8192,1024] @ [1024,3072]
    tf32gemm_kernel<0><<<dim3(QKVDIM / 128, MROWS / 128), 256>>>(
        h, wqkv, qkv, nullptr, nullptr, MROWS, QKVDIM, CDIM);

    // 4) attention
    size_t fasm = (size_t)(3 * 64 * 65 + 64 * 64) * sizeof(float);
    cudaFuncSetAttribute(flash_attn_kernel, cudaFuncAttributeMaxDynamicSharedMemorySize, (int)fasm);
    flash_attn_kernel<<<dim3(TSEQ / 64, NHEAD, BATCH), 256, fasm>>>(qkv, attn);

    // 5) output projection + residual: x1 = x + attn@Wp + bp
    tf32gemm_kernel<3><<<dim3(CDIM / 128, MROWS / 128), 256>>>(
        attn, Wp, x1, bp, x, MROWS, CDIM, CDIM);

    // 6) LN2
    layernorm_kernel<<<MROWS, 256>>>(x1, ln2g, ln2b, h);

    // 7) ff = relu(h@W1 + b1)
    tf32gemm_kernel<2><<<dim3(FDIM / 128, MROWS / 128), 256>>>(
        h, W1, ff, b1, nullptr, MROWS, FDIM, CDIM);

    // 8) out = x1 + ff@W2 + b2
    tf32gemm_kernel<3><<<dim3(CDIM / 128, MROWS / 128), 256>>>(
        ff, W2, out, b2, x1, MROWS, CDIM, FDIM);
}

// round 3
// speedup vs baseline: 3.3937x; 1.4558x over previous
#include <cuda_runtime.h>
#include <cuda_bf16.h>
#include <cstdint>

// Problem constants
#define BATCH   4
#define TSEQ    2048
#define CDIM    1024
#define NHEAD   16
#define HDIM    64
#define FDIM    4096
#define MROWS   (BATCH * TSEQ)          // 8192
#define QKVDIM  (3 * CDIM)              // 3072
#define SM_SCALE 0.03125f               // C^-0.5 = 1/32

// ---------------- scratch (static device globals; no allocation) ----------------
__device__ float g_h   [MROWS * CDIM];    // LN output (reused for LN1 and LN2)
__device__ float g_qkv [MROWS * QKVDIM];  // [M, 3C]: q | k | v, each [B,T,H,D]
__device__ float g_attn[MROWS * CDIM];    // [B,T,H,D] == concat-heads [M,C]
__device__ float g_x1  [MROWS * CDIM];    // x + attn@Wp + bp
__device__ float g_ff  [MROWS * FDIM];    // relu(h@W1+b1)
__device__ float g_wqkv[CDIM * QKVDIM];   // packed [C, 3C]

// ---------------- helpers ----------------
__device__ __forceinline__ uint32_t tf32c(float x) {
    uint32_t r;
    asm("cvt.rna.tf32.f32 %0, %1;" : "=r"(r) : "f"(x));
    return r;
}
__device__ __forceinline__ void cp16(void* smem, const void* gsrc) {
    uint32_t s = (uint32_t)__cvta_generic_to_shared(smem);
    asm volatile("cp.async.cg.shared.global [%0], [%1], 16;\n" :: "r"(s), "l"(gsrc));
}
__device__ __forceinline__ void mma_tf32(float* c, const uint32_t* a, const uint32_t* b) {
    asm volatile(
        "mma.sync.aligned.m16n8k8.row.col.f32.tf32.tf32.f32 "
        "{%0,%1,%2,%3}, {%4,%5,%6,%7}, {%8,%9}, {%0,%1,%2,%3};\n"
        : "+f"(c[0]), "+f"(c[1]), "+f"(c[2]), "+f"(c[3])
        : "r"(a[0]), "r"(a[1]), "r"(a[2]), "r"(a[3]), "r"(b[0]), "r"(b[1]));
}

// ---------------- pack Wq/Wk/Wv from [H,C,D] into [C, 3C] ----------------
__global__ void pack_w_kernel(const float* __restrict__ Wq, const float* __restrict__ Wk,
                              const float* __restrict__ Wv) {
    int idx = blockIdx.x * 256 + threadIdx.x;   // over C*C = 1M
    int h = idx >> 16;
    int c = (idx >> 6) & 1023;
    int d = idx & 63;
    int o = c * QKVDIM + h * HDIM + d;
    g_wqkv[o]            = Wq[idx];
    g_wqkv[o + CDIM]     = Wk[idx];
    g_wqkv[o + 2 * CDIM] = Wv[idx];
}

// ---------------- layernorm ----------------
__global__ void layernorm_kernel(const float* __restrict__ x, const float* __restrict__ g,
                                 const float* __restrict__ b, float* __restrict__ out) {
    const int row = blockIdx.x;
    const int t = threadIdx.x;
    const size_t off = (size_t)row * CDIM + t * 4;
    float4 v = *(const float4*)(x + off);
    float s  = v.x + v.y + v.z + v.w;
    float ss = fmaf(v.x, v.x, fmaf(v.y, v.y, fmaf(v.z, v.z, v.w * v.w)));
#pragma unroll
    for (int o = 16; o; o >>= 1) {
        s  += __shfl_xor_sync(0xffffffffu, s,  o);
        ss += __shfl_xor_sync(0xffffffffu, ss, o);
    }
    __shared__ float ws[8], wss[8];
    __shared__ float s_mu, s_rs;
    int lane = t & 31, wid = t >> 5;
    if (lane == 0) { ws[wid] = s; wss[wid] = ss; }
    __syncthreads();
    if (t == 0) {
        float S = 0.f, SS = 0.f;
#pragma unroll
        for (int i = 0; i < 8; ++i) { S += ws[i]; SS += wss[i]; }
        float mu  = S * (1.f / CDIM);
        float var = SS * (1.f / CDIM) - mu * mu;
        s_mu = mu;
        s_rs = rsqrtf(var + 1e-5f);
    }
    __syncthreads();
    float mu = s_mu, rs = s_rs;
    float4 gv = *(const float4*)(g + t * 4);
    float4 bv = *(const float4*)(b + t * 4);
    float4 ov;
    ov.x = (v.x - mu) * rs * gv.x + bv.x;
    ov.y = (v.y - mu) * rs * gv.y + bv.y;
    ov.z = (v.z - mu) * rs * gv.z + bv.z;
    ov.w = (v.w - mu) * rs * gv.w + bv.w;
    *(float4*)(out + off) = ov;
}

// ---------------- TF32 tensor-core GEMM (unchanged from round 2) ----------------
#define AS_STRIDE 20
#define BS_STRIDE 136

template <int EPI>
__global__ __launch_bounds__(256, 2)
void tf32gemm_kernel(const float* __restrict__ A, const float* __restrict__ Bm,
                     float* __restrict__ Cm, const float* __restrict__ bias,
                     const float* __restrict__ res, int M, int N, int K) {
    __shared__ float As[2][128][AS_STRIDE];
    __shared__ float Bs[2][16][BS_STRIDE];

    const int tid  = threadIdx.x;
    const int lane = tid & 31, wid = tid >> 5;
    const int warpM = wid & 1;
    const int warpN = wid >> 1;
    const int row0 = blockIdx.y * 128, col0 = blockIdx.x * 128;
    const int g  = lane >> 2;
    const int tg = lane & 3;

    const int arow = tid >> 2, ac4 = (tid & 3) * 4;
    const int bkr  = tid >> 5, bn4 = (tid & 31) * 4;

    float acc[4][4][4];
#pragma unroll
    for (int mt = 0; mt < 4; ++mt)
#pragma unroll
        for (int nt = 0; nt < 4; ++nt)
#pragma unroll
            for (int r = 0; r < 4; ++r) acc[mt][nt][r] = 0.f;

#define LOAD_STAGE(s, k0)                                                            \
    do {                                                                             \
        cp16(&As[s][arow][ac4],      A + (size_t)(row0 + arow) * K + (k0) + ac4);    \
        cp16(&As[s][arow + 64][ac4], A + (size_t)(row0 + arow + 64) * K + (k0) + ac4);\
        cp16(&Bs[s][bkr][bn4],       Bm + (size_t)((k0) + bkr) * N + col0 + bn4);    \
        cp16(&Bs[s][bkr + 8][bn4],   Bm + (size_t)((k0) + bkr + 8) * N + col0 + bn4);\
        asm volatile("cp.async.commit_group;\n");                                    \
    } while (0)

    LOAD_STAGE(0, 0);
    const int KT = K >> 4;
    for (int kt = 0; kt < KT; ++kt) {
        if (kt + 1 < KT) {
            LOAD_STAGE((kt + 1) & 1, (kt + 1) << 4);
            asm volatile("cp.async.wait_group 1;\n");
        } else {
            asm volatile("cp.async.wait_group 0;\n");
        }
        __syncthreads();
        const int s = kt & 1;
#pragma unroll
        for (int ch = 0; ch < 2; ++ch) {
            const int kc = ch * 8;
            uint32_t a[4][4], b[4][2];
#pragma unroll
            for (int mt = 0; mt < 4; ++mt) {
                const int r = warpM * 64 + mt * 16 + g;
                const int c = kc + tg;
                a[mt][0] = tf32c(As[s][r][c]);
                a[mt][1] = tf32c(As[s][r + 8][c]);
                a[mt][2] = tf32c(As[s][r][c + 4]);
                a[mt][3] = tf32c(As[s][r + 8][c + 4]);
            }
#pragma unroll
            for (int nt = 0; nt < 4; ++nt) {
                const int n = warpN * 32 + nt * 8 + g;
                const int k = kc + tg;
                b[nt][0] = tf32c(Bs[s][k][n]);
                b[nt][1] = tf32c(Bs[s][k + 4][n]);
            }
#pragma unroll
            for (int mt = 0; mt < 4; ++mt)
#pragma unroll
                for (int nt = 0; nt < 4; ++nt)
                    mma_tf32(acc[mt][nt], a[mt], b[nt]);
        }
        __syncthreads();
    }
#undef LOAD_STAGE

#pragma unroll
    for (int mt = 0; mt < 4; ++mt) {
#pragma unroll
        for (int nt = 0; nt < 4; ++nt) {
            const int r = row0 + warpM * 64 + mt * 16 + g;
            const int c = col0 + warpN * 32 + nt * 8 + 2 * tg;
            float2 v0 = make_float2(acc[mt][nt][0], acc[mt][nt][1]);
            float2 v1 = make_float2(acc[mt][nt][2], acc[mt][nt][3]);
            if (EPI >= 2) {
                float b0 = bias[c], b1 = bias[c + 1];
                v0.x += b0; v0.y += b1;
                v1.x += b0; v1.y += b1;
            }
            if (EPI == 2) {
                v0.x = fmaxf(v0.x, 0.f); v0.y = fmaxf(v0.y, 0.f);
                v1.x = fmaxf(v1.x, 0.f); v1.y = fmaxf(v1.y, 0.f);
            }
            if (EPI == 3) {
                float2 r0 = *(const float2*)(res + (size_t)r * N + c);
                float2 r1 = *(const float2*)(res + (size_t)(r + 8) * N + c);
                v0.x += r0.x; v0.y += r0.y;
                v1.x += r1.x; v1.y += r1.y;
            }
            *(float2*)(Cm + (size_t)r * N + c)       = v0;
            *(float2*)(Cm + (size_t)(r + 8) * N + c) = v1;
        }
    }
}

// ---------------- tensor-core flash attention (TF32 mma), causal ----------------
// grid (T/64, H, B), 128 threads = 4 warps; warp w owns Q rows w*16..w*16+15.
// smem strides chosen conflict-free for the mma fragment access patterns:
//   P/Q staging stride 68: bank = 4g+tg (distinct)
//   Ks stride 76:         bank = 12g+tg (distinct)
//   Vs stride 72:         bank = 8tg+g  (distinct)
#define PS_STR 68
#define KS_STR 76
#define VS_STR 72
#define FA_SMEM ((64 * PS_STR + 64 * KS_STR + 64 * VS_STR) * 4)

__global__ __launch_bounds__(128)
void flash_attn_tc_kernel(const float* __restrict__ QKV, float* __restrict__ O) {
    extern __shared__ float sm[];
    float* Ps = sm;                              // [64][68] (also Q staging)
    float* Ks = sm + 64 * PS_STR;                // [64][76]
    float* Vs = sm + 64 * PS_STR + 64 * KS_STR;  // [64][72]

    const int qb = blockIdx.x, h = blockIdx.y, b = blockIdx.z;
    const int tid = threadIdx.x, lane = tid & 31, w = tid >> 5;
    const int g = lane >> 2, tg = lane & 3;
    const int q0 = qb * 64;
    const int mrow = w * 16;
    const size_t base  = (size_t)b * TSEQ * QKVDIM + h * HDIM;
    const size_t obase = (size_t)b * TSEQ * CDIM + h * HDIM;
    const float* Q = QKV;
    const float* K = QKV + CDIM;
    const float* V = QKV + 2 * CDIM;

    // stage Q tile into Ps region, extract per-warp fragments into registers
    for (int i = tid; i < 64 * 16; i += 128) {
        int r = i >> 4, c4 = (i & 15) * 4;
        float4 qv = *(const float4*)(Q + base + (size_t)(q0 + r) * QKVDIM + c4);
        float* dst = Ps + r * PS_STR + c4;
        dst[0] = qv.x; dst[1] = qv.y; dst[2] = qv.z; dst[3] = qv.w;
    }
    __syncthreads();
    uint32_t qf[8][4];
#pragma unroll
    for (int kc = 0; kc < 8; ++kc) {
        const int c = kc * 8;
        qf[kc][0] = tf32c(Ps[(mrow + g)     * PS_STR + c + tg]);
        qf[kc][1] = tf32c(Ps[(mrow + g + 8) * PS_STR + c + tg]);
        qf[kc][2] = tf32c(Ps[(mrow + g)     * PS_STR + c + tg + 4]);
        qf[kc][3] = tf32c(Ps[(mrow + g + 8) * PS_STR + c + tg + 4]);
    }
    __syncthreads();

    float oacc[8][4];
#pragma unroll
    for (int n = 0; n < 8; ++n)
#pragma unroll
        for (int r = 0; r < 4; ++r) oacc[n][r] = 0.f;
    float m0 = -1e30f, m1 = -1e30f, l0 = 0.f, l1 = 0.f;

    for (int j = 0; j <= qb; ++j) {
        const int k0 = j * 64;
        for (int i = tid; i < 64 * 16; i += 128) {
            int r = i >> 4, c4 = (i & 15) * 4;
            float4 kv = *(const float4*)(K + base + (size_t)(k0 + r) * QKVDIM + c4);
            float* kd = Ks + r * KS_STR + c4;
            kd[0] = kv.x; kd[1] = kv.y; kd[2] = kv.z; kd[3] = kv.w;
            float4 vv = *(const float4*)(V + base + (size_t)(k0 + r) * QKVDIM + c4);
            float* vd = Vs + r * VS_STR + c4;
            vd[0] = vv.x; vd[1] = vv.y; vd[2] = vv.z; vd[3] = vv.w;
        }
        __syncthreads();

        // ---- S = Q K^T (16 x 64 per warp) ----
        float sacc[8][4];
#pragma unroll
        for (int n = 0; n < 8; ++n) {
#pragma unroll
            for (int r = 0; r < 4; ++r) sacc[n][r] = 0.f;
        }
#pragma unroll
        for (int n = 0; n < 8; ++n) {
            const float* krow = Ks + (n * 8 + g) * KS_STR;
#pragma unroll
            for (int kc = 0; kc < 8; ++kc) {
                uint32_t bb[2];
                bb[0] = tf32c(krow[kc * 8 + tg]);
                bb[1] = tf32c(krow[kc * 8 + tg + 4]);
                mma_tf32(sacc[n], qf[kc], bb);
            }
        }

        // ---- online softmax ----
        const bool diag = (j == qb);
#pragma unroll
        for (int n = 0; n < 8; ++n) {
            sacc[n][0] *= SM_SCALE; sacc[n][1] *= SM_SCALE;
            sacc[n][2] *= SM_SCALE; sacc[n][3] *= SM_SCALE;
            if (diag) {
                const int c0 = n * 8 + 2 * tg, c1 = c0 + 1;
                const int r0 = mrow + g, r1 = r0 + 8;
                if (c0 > r0) sacc[n][0] = -1e30f;
                if (c1 > r0) sacc[n][1] = -1e30f;
                if (c0 > r1) sacc[n][2] = -1e30f;
                if (c1 > r1) sacc[n][3] = -1e30f;
            }
        }
        float mx0 = -1e30f, mx1 = -1e30f;
#pragma unroll
        for (int n = 0; n < 8; ++n) {
            mx0 = fmaxf(mx0, fmaxf(sacc[n][0], sacc[n][1]));
            mx1 = fmaxf(mx1, fmaxf(sacc[n][2], sacc[n][3]));
        }
        mx0 = fmaxf(mx0, __shfl_xor_sync(0xffffffffu, mx0, 1));
        mx0 = fmaxf(mx0, __shfl_xor_sync(0xffffffffu, mx0, 2));
        mx1 = fmaxf(mx1, __shfl_xor_sync(0xffffffffu, mx1, 1));
        mx1 = fmaxf(mx1, __shfl_xor_sync(0xffffffffu, mx1, 2));
        const float mn0 = fmaxf(m0, mx0), mn1 = fmaxf(m1, mx1);
        const float al0 = __expf(m0 - mn0), al1 = __expf(m1 - mn1);
        m0 = mn0; m1 = mn1;

        float sum0 = 0.f, sum1 = 0.f;
        float* prow0 = Ps + (mrow + g) * PS_STR;
        float* prow1 = Ps + (mrow + g + 8) * PS_STR;
#pragma unroll
        for (int n = 0; n < 8; ++n) {
            float p00 = __expf(sacc[n][0] - mn0);
            float p01 = __expf(sacc[n][1] - mn0);
            float p10 = __expf(sacc[n][2] - mn1);
            float p11 = __expf(sacc[n][3] - mn1);
            sum0 += p00 + p01;
            sum1 += p10 + p11;
            const int c = n * 8 + 2 * tg;
            prow0[c]     = __uint_as_float(tf32c(p00));
            prow0[c + 1] = __uint_as_float(tf32c(p01));
            prow1[c]     = __uint_as_float(tf32c(p10));
            prow1[c + 1] = __uint_as_float(tf32c(p11));
        }
        sum0 += __shfl_xor_sync(0xffffffffu, sum0, 1);
        sum0 += __shfl_xor_sync(0xffffffffu, sum0, 2);
        sum1 += __shfl_xor_sync(0xffffffffu, sum1, 1);
        sum1 += __shfl_xor_sync(0xffffffffu, sum1, 2);
        l0 = l0 * al0 + sum0;
        l1 = l1 * al1 + sum1;
#pragma unroll
        for (int n = 0; n < 8; ++n) {
            oacc[n][0] *= al0; oacc[n][1] *= al0;
            oacc[n][2] *= al1; oacc[n][3] *= al1;
        }
        __syncwarp();

        // ---- O += P V ----
#pragma unroll
        for (int kc = 0; kc < 8; ++kc) {
            uint32_t aa[4];
            aa[0] = __float_as_uint(Ps[(mrow + g)     * PS_STR + kc * 8 + tg]);
            aa[1] = __float_as_uint(Ps[(mrow + g + 8) * PS_STR + kc * 8 + tg]);
            aa[2] = __float_as_uint(Ps[(mrow + g)     * PS_STR + kc * 8 + tg + 4]);
            aa[3] = __float_as_uint(Ps[(mrow + g + 8) * PS_STR + kc * 8 + tg + 4]);
            const float* v0 = Vs + (kc * 8 + tg) * VS_STR;
            const float* v1 = Vs + (kc * 8 + tg + 4) * VS_STR;
#pragma unroll
            for (int n = 0; n < 8; ++n) {
                uint32_t bb[2];
                bb[0] = tf32c(v0[n * 8 + g]);
                bb[1] = tf32c(v1[n * 8 + g]);
                mma_tf32(oacc[n], aa, bb);
            }
        }
        __syncthreads();
    }

    const float inv0 = 1.f / l0, inv1 = 1.f / l1;
    const int r0 = q0 + mrow + g, r1 = r0 + 8;
#pragma unroll
    for (int n = 0; n < 8; ++n) {
        const int c = n * 8 + 2 * tg;
        *(float2*)(O + obase + (size_t)r0 * CDIM + c) =
            make_float2(oacc[n][0] * inv0, oacc[n][1] * inv0);
        *(float2*)(O + obase + (size_t)r1 * CDIM + c) =
            make_float2(oacc[n][2] * inv1, oacc[n][3] * inv1);
    }
}

// ---------------- launch ----------------
extern "C" void kernel_launch(void* const* d_in, const int* in_sizes, int n_in,
                              void* d_out, int out_size) {
    (void)in_sizes; (void)n_in; (void)out_size;
    const float* x    = (const float*)d_in[0];
    const float* Wq   = (const float*)d_in[1];
    const float* Wk   = (const float*)d_in[2];
    const float* Wv   = (const float*)d_in[3];
    const float* Wp   = (const float*)d_in[4];
    const float* bp   = (const float*)d_in[5];
    const float* ln1g = (const float*)d_in[6];
    const float* ln1b = (const float*)d_in[7];
    const float* ln2g = (const float*)d_in[8];
    const float* ln2b = (const float*)d_in[9];
    const float* W1   = (const float*)d_in[10];
    const float* b1   = (const float*)d_in[11];
    const float* W2   = (const float*)d_in[12];
    const float* b2   = (const float*)d_in[13];
    float* out = (float*)d_out;

    float *h, *qkv, *attn, *x1, *ff, *wqkv;
    cudaGetSymbolAddress((void**)&h,    g_h);
    cudaGetSymbolAddress((void**)&qkv,  g_qkv);
    cudaGetSymbolAddress((void**)&attn, g_attn);
    cudaGetSymbolAddress((void**)&x1,   g_x1);
    cudaGetSymbolAddress((void**)&ff,   g_ff);
    cudaGetSymbolAddress((void**)&wqkv, g_wqkv);

    // 1) pack QKV weights [H,C,D] -> [C, 3C]
    pack_w_kernel<<<(CDIM * CDIM) / 256, 256>>>(Wq, Wk, Wv);

    // 2) LN1
    layernorm_kernel<<<MROWS, 256>>>(x, ln1g, ln1b, h);

    // 3) fused QKV projection: [8192,1024] @ [1024,3072]
    tf32gemm_kernel<0><<<dim3(QKVDIM / 128, MROWS / 128), 256>>>(
        h, wqkv, qkv, nullptr, nullptr, MROWS, QKVDIM, CDIM);

    // 4) attention (tensor-core flash)
    cudaFuncSetAttribute(flash_attn_tc_kernel,
                         cudaFuncAttributeMaxDynamicSharedMemorySize, FA_SMEM);
    flash_attn_tc_kernel<<<dim3(TSEQ / 64, NHEAD, BATCH), 128, FA_SMEM>>>(qkv, attn);

    // 5) output projection + residual: x1 = x + attn@Wp + bp
    tf32gemm_kernel<3><<<dim3(CDIM / 128, MROWS / 128), 256>>>(
        attn, Wp, x1, bp, x, MROWS, CDIM, CDIM);

    // 6) LN2
    layernorm_kernel<<<MROWS, 256>>>(x1, ln2g, ln2b, h);

    // 7) ff = relu(h@W1 + b1)
    tf32gemm_kernel<2><<<dim3(FDIM / 128, MROWS / 128), 256>>>(
        h, W1, ff, b1, nullptr, MROWS, FDIM, CDIM);

    // 8) out = x1 + ff@W2 + b2
    tf32gemm_kernel<3><<<dim3(CDIM / 128, MROWS / 128), 256>>>(
        ff, W2, out, b2, x1, MROWS, CDIM, FDIM);
}